// round 14
// baseline (speedup 1.0000x reference)
#include <cuda_runtime.h>
#include <cuda_fp16.h>
#include <math.h>
#include <stdint.h>

#define BB   2
#define DD   2048
#define HH   16
#define DHD  128
#define TT   1280
#define LL   2048
#define LIP  512
#define MM   2560      // LL + LIP
#define TWOD 4096

// ------------------------- device scratch -------------------------
__device__ float  g_emb[BB * TWOD];
__device__ __half g_ipn[BB * LIP * DD];
__device__ float  g_ipk[BB * LIP * DD];
__device__ float  g_ipv[BB * LIP * DD];
__device__ __half g_wk[DD * DD];
__device__ __half g_wv[DD * DD];
__device__ __half g_q[(size_t)BB * HH * LL * DHD];        // fp16 q (rms * log2e/sqrt(d))
__device__ __half g_k[(size_t)BB * HH * MM * DHD];
__device__ __half g_v[(size_t)BB * HH * MM * DHD];

// ------------------------- helpers -------------------------
__device__ __forceinline__ void mma16f16(float* d, const unsigned* a, unsigned b0, unsigned b1) {
    asm volatile(
        "mma.sync.aligned.m16n8k16.row.col.f32.f16.f16.f32 "
        "{%0,%1,%2,%3},{%4,%5,%6,%7},{%8,%9},{%0,%1,%2,%3};"
        : "+f"(d[0]), "+f"(d[1]), "+f"(d[2]), "+f"(d[3])
        : "r"(a[0]), "r"(a[1]), "r"(a[2]), "r"(a[3]), "r"(b0), "r"(b1));
}
__device__ __forceinline__ void ldsm4(unsigned* r, uint32_t saddr) {
    asm volatile("ldmatrix.sync.aligned.m8n8.x4.shared.b16 {%0,%1,%2,%3}, [%4];"
        : "=r"(r[0]), "=r"(r[1]), "=r"(r[2]), "=r"(r[3]) : "r"(saddr));
}
__device__ __forceinline__ void ldsm4t(unsigned* r, uint32_t saddr) {
    asm volatile("ldmatrix.sync.aligned.m8n8.x4.trans.shared.b16 {%0,%1,%2,%3}, [%4];"
        : "=r"(r[0]), "=r"(r[1]), "=r"(r[2]), "=r"(r[3]) : "r"(saddr));
}
__device__ __forceinline__ void ldsm2t(unsigned* r, uint32_t saddr) {
    asm volatile("ldmatrix.sync.aligned.m8n8.x2.trans.shared.b16 {%0,%1}, [%2];"
        : "=r"(r[0]), "=r"(r[1]) : "r"(saddr));
}
__device__ __forceinline__ void stsm4(uint32_t saddr, unsigned r0, unsigned r1,
                                      unsigned r2, unsigned r3) {
    asm volatile("stmatrix.sync.aligned.m8n8.x4.shared.b16 [%0], {%1,%2,%3,%4};"
        :: "r"(saddr), "r"(r0), "r"(r1), "r"(r2), "r"(r3) : "memory");
}
__device__ __forceinline__ float ex2f(float x) {
    float y; asm("ex2.approx.f32 %0, %1;" : "=f"(y) : "f"(x));
    return y;
}
__device__ __forceinline__ uint32_t smem_u32(const void* p) {
    return (uint32_t)__cvta_generic_to_shared(p);
}
__device__ __forceinline__ void cp16(void* s, const void* g) {
    unsigned a = (unsigned)__cvta_generic_to_shared(s);
    asm volatile("cp.async.cg.shared.global [%0], [%1], 16;" :: "r"(a), "l"(g));
}
#define CPCOMMIT asm volatile("cp.async.commit_group;")
#define CPWAIT(N) asm volatile("cp.async.wait_group %0;" :: "n"(N))

// ------------------------- kernel 0: weights -> fp16 -------------------------
__global__ void k_round(const float* __restrict__ Wk, const float* __restrict__ Wv) {
    int i = blockIdx.x * blockDim.x + threadIdx.x;
    float4 a0 = *(const float4*)(Wk + (size_t)i * 8);
    float4 a1 = *(const float4*)(Wk + (size_t)i * 8 + 4);
    float4 b0 = *(const float4*)(Wv + (size_t)i * 8);
    float4 b1 = *(const float4*)(Wv + (size_t)i * 8 + 4);
    __half2 ha[4] = { __floats2half2_rn(a0.x, a0.y), __floats2half2_rn(a0.z, a0.w),
                      __floats2half2_rn(a1.x, a1.y), __floats2half2_rn(a1.z, a1.w) };
    __half2 hb[4] = { __floats2half2_rn(b0.x, b0.y), __floats2half2_rn(b0.z, b0.w),
                      __floats2half2_rn(b1.x, b1.y), __floats2half2_rn(b1.z, b1.w) };
    *(uint4*)(g_wk + (size_t)i * 8) = *(uint4*)ha;
    *(uint4*)(g_wv + (size_t)i * 8) = *(uint4*)hb;
}

// ------------------------- kernel 1: emb -------------------------
__global__ void k_emb(const float* __restrict__ t_emb, const float* __restrict__ W,
                      const float* __restrict__ bias) {
    int gw   = (blockIdx.x * blockDim.x + threadIdx.x) >> 5;
    int lane = threadIdx.x & 31;
    int b = gw >> 12;
    int j = gw & 4095;
    const float* t = t_emb + b * TT;
    const float* w = W + (size_t)j * TT;
    float acc = 0.f;
    #pragma unroll
    for (int i = lane * 4; i < TT; i += 128) {
        float4 tv = *(const float4*)(t + i);
        float4 wv = *(const float4*)(w + i);
        acc += tv.x / (1.f + __expf(-tv.x)) * wv.x;
        acc += tv.y / (1.f + __expf(-tv.y)) * wv.y;
        acc += tv.z / (1.f + __expf(-tv.z)) * wv.z;
        acc += tv.w / (1.f + __expf(-tv.w)) * wv.w;
    }
    #pragma unroll
    for (int o = 16; o; o >>= 1) acc += __shfl_xor_sync(0xffffffffu, acc, o);
    if (lane == 0) g_emb[gw] = acc + bias[j];
}

// ------------------------- kernel 2: adaLN -> fp16 -------------------------
__global__ void k_ipnorm(const float* __restrict__ ip) {
    __shared__ float red[64];
    int row = blockIdx.x;
    int b = row / LIP;
    const float* x = ip + (size_t)row * DD;
    int i0 = threadIdx.x * 8;
    float4 v0 = *(const float4*)(x + i0);
    float4 v1 = *(const float4*)(x + i0 + 4);
    float s  = v0.x + v0.y + v0.z + v0.w + v1.x + v1.y + v1.z + v1.w;
    float ss = v0.x*v0.x + v0.y*v0.y + v0.z*v0.z + v0.w*v0.w
             + v1.x*v1.x + v1.y*v1.y + v1.z*v1.z + v1.w*v1.w;
    #pragma unroll
    for (int o = 16; o; o >>= 1) {
        s  += __shfl_xor_sync(0xffffffffu, s,  o);
        ss += __shfl_xor_sync(0xffffffffu, ss, o);
    }
    int w = threadIdx.x >> 5, lane = threadIdx.x & 31;
    if (lane == 0) { red[w] = s; red[32 + w] = ss; }
    __syncthreads();
    float fs = 0.f, fss = 0.f;
    #pragma unroll
    for (int k = 0; k < 8; k++) { fs += red[k]; fss += red[32 + k]; }
    float mu   = fs * (1.f / DD);
    float var  = fss * (1.f / DD) - mu * mu;
    float rstd = rsqrtf(var + 1e-6f);
    const float* shp = g_emb + b * TWOD;
    const float* scp = shp + DD;
    __half* y = g_ipn + (size_t)row * DD;
    float4 sh0 = *(const float4*)(shp + i0), sh1 = *(const float4*)(shp + i0 + 4);
    float4 sc0 = *(const float4*)(scp + i0), sc1 = *(const float4*)(scp + i0 + 4);
    __half2 h[4];
    h[0] = __floats2half2_rn((v0.x - mu) * rstd * (1.f + sc0.x) + sh0.x,
                             (v0.y - mu) * rstd * (1.f + sc0.y) + sh0.y);
    h[1] = __floats2half2_rn((v0.z - mu) * rstd * (1.f + sc0.z) + sh0.z,
                             (v0.w - mu) * rstd * (1.f + sc0.w) + sh0.w);
    h[2] = __floats2half2_rn((v1.x - mu) * rstd * (1.f + sc1.x) + sh1.x,
                             (v1.y - mu) * rstd * (1.f + sc1.y) + sh1.y);
    h[3] = __floats2half2_rn((v1.z - mu) * rstd * (1.f + sc1.z) + sh1.z,
                             (v1.w - mu) * rstd * (1.f + sc1.w) + sh1.w);
    *(uint4*)(y + i0) = *(uint4*)h;
}

// ------------------------- kernel 3: fp16 GEMM, fp32 accum (R9 structure) -------------------------
#define GST 40
#define GNST 3
__global__ void __launch_bounds__(256, 2) k_gemm() {
    extern __shared__ __half hsm[];
    __half* a_s = hsm;
    __half* b_s = hsm + GNST * 128 * GST;
    const __half* A  = g_ipn;
    const __half* Bw = blockIdx.z ? g_wv : g_wk;
    float*        C  = blockIdx.z ? g_ipv : g_ipk;
    int m0 = blockIdx.y * 128, n0 = blockIdx.x * 128;
    int tid = threadIdx.x, w = tid >> 5, lane = tid & 31;
    int g = lane >> 2, q = lane & 3;
    int mi = lane >> 3, r = lane & 7;
    int wm = (w & 3) * 32, wn = (w >> 2) * 64;
    uint32_t aoff = ((mi & 1) * 8 + r) * GST + (mi >> 1) * 8;
    uint32_t boff = ((mi >> 1) * 8 + r) * GST + (mi & 1) * 8;
    float c[2][8][4] = {};

    auto issue = [&](int ch) {
        int st = ch % GNST;
        __half* ad = a_s + st * 128 * GST;
        __half* bd = b_s + st * 128 * GST;
        #pragma unroll
        for (int i = 0; i < 2; i++) {
            int idx = tid + i * 256;
            int rr = idx >> 2, cc = (idx & 3) * 8;
            cp16(ad + rr * GST + cc, A  + (size_t)(m0 + rr) * DD + ch * 32 + cc);
            cp16(bd + rr * GST + cc, Bw + (size_t)(n0 + rr) * DD + ch * 32 + cc);
        }
        CPCOMMIT;
    };
    issue(0); issue(1);

    #pragma unroll 1
    for (int ch = 0; ch < 64; ch++) {
        if (ch < 63) CPWAIT(1); else CPWAIT(0);
        __syncthreads();
        int st = ch % GNST;
        uint32_t au = smem_u32(a_s + st * 128 * GST);
        uint32_t bu = smem_u32(b_s + st * 128 * GST);
        #pragma unroll
        for (int ks = 0; ks < 2; ks++) {
            unsigned af[2][4];
            #pragma unroll
            for (int i = 0; i < 2; i++)
                ldsm4(af[i], au + 2 * ((wm + 16 * i) * GST + ks * 16 + aoff));
            #pragma unroll
            for (int j2 = 0; j2 < 4; j2++) {
                unsigned bf[4];
                ldsm4(bf, bu + 2 * ((wn + 16 * j2) * GST + ks * 16 + boff));
                mma16f16(c[0][2 * j2],     af[0], bf[0], bf[1]);
                mma16f16(c[0][2 * j2 + 1], af[0], bf[2], bf[3]);
                mma16f16(c[1][2 * j2],     af[1], bf[0], bf[1]);
                mma16f16(c[1][2 * j2 + 1], af[1], bf[2], bf[3]);
            }
        }
        __syncthreads();
        if (ch + 2 < 64) issue(ch + 2);
    }
    #pragma unroll
    for (int i = 0; i < 2; i++)
        #pragma unroll
        for (int j = 0; j < 8; j++) {
            int r0 = m0 + wm + 16 * i + g, cc = n0 + wn + 8 * j + 2 * q;
            *(float2*)(C + (size_t)r0 * DD + cc)       = make_float2(c[i][j][0], c[i][j][1]);
            *(float2*)(C + (size_t)(r0 + 8) * DD + cc) = make_float2(c[i][j][2], c[i][j][3]);
        }
}

// ------------------------- kernel 4: RMS-norm + head split/scatter -> fp16 -------------------------
__global__ void k_scatter(const float* __restrict__ q, const float* __restrict__ k,
                          const float* __restrict__ v,
                          const float* __restrict__ wq, const float* __restrict__ wk,
                          const float* __restrict__ wipk) {
    int gw   = (blockIdx.x * blockDim.x + threadIdx.x) >> 5;
    int lane = threadIdx.x & 31;
    const int NQ  = BB * HH * LL;
    const int NIP = BB * HH * LIP;
    const float* src; __half* dst; const float* wptr = nullptr;
    float scale = 1.f; bool do_rms = false;

    int idx = gw;
    if (idx < NQ) {
        int b = idx / (HH * LL), r = idx % (HH * LL), h = r / LL, l = r % LL;
        src = q + (size_t)(b * LL + l) * DD + h * DHD;
        dst = g_q + (size_t)idx * DHD;
        wptr = wq; do_rms = true;
        scale = 1.4426950408889634f * 0.08838834764831845f;   // log2e / sqrt(128)
    } else if ((idx -= NQ) < NQ) {
        int b = idx / (HH * LL), r = idx % (HH * LL), h = r / LL, l = r % LL;
        src = k + (size_t)(b * LL + l) * DD + h * DHD;
        dst = g_k + ((size_t)(b * HH + h) * MM + l) * DHD;
        wptr = wk; do_rms = true;
    } else if ((idx -= NQ) < NIP) {
        int b = idx / (HH * LIP), r = idx % (HH * LIP), h = r / LIP, l = r % LIP;
        src = g_ipk + (size_t)(b * LIP + l) * DD + h * DHD;
        dst = g_k + ((size_t)(b * HH + h) * MM + LL + l) * DHD;
        wptr = wipk; do_rms = true;
    } else if ((idx -= NIP) < NQ) {
        int b = idx / (HH * LL), r = idx % (HH * LL), h = r / LL, l = r % LL;
        src = v + (size_t)(b * LL + l) * DD + h * DHD;
        dst = g_v + ((size_t)(b * HH + h) * MM + l) * DHD;
    } else {
        idx -= NQ;
        int b = idx / (HH * LIP), r = idx % (HH * LIP), h = r / LIP, l = r % LIP;
        src = g_ipv + (size_t)(b * LIP + l) * DD + h * DHD;
        dst = g_v + ((size_t)(b * HH + h) * MM + LL + l) * DHD;
    }

    float4 val = *(const float4*)(src + lane * 4);
    if (do_rms) {
        float ss = val.x*val.x + val.y*val.y + val.z*val.z + val.w*val.w;
        #pragma unroll
        for (int o = 16; o; o >>= 1) ss += __shfl_xor_sync(0xffffffffu, ss, o);
        float r = rsqrtf(ss * (1.f / DHD) + 1e-6f) * scale;
        float4 w4 = *(const float4*)(wptr + lane * 4);
        val.x *= r * w4.x; val.y *= r * w4.y; val.z *= r * w4.z; val.w *= r * w4.w;
    }
    __half2 h0 = __floats2half2_rn(val.x, val.y);
    __half2 h1 = __floats2half2_rn(val.z, val.w);
    *(__half2*)(dst + lane * 4)     = h0;
    *(__half2*)(dst + lane * 4 + 2) = h1;
}

// ------------------------- kernel 5: flash attention, 4x2 warp-tiled, P round-trip -------------------------
// CTA: 256 threads (8 warps), 1 CTA/SM. Q tile 128; warp (mg,ng): S[32x32], O[32x64].
// KV 3-stage ring; P double-buffered via stmatrix/ldmatrix; l via ones-pad column mma.
#define VSTK 136
#define KVT  64
#define NIT  (MM / KVT)   // 40
#define PST  72           // P row stride (halves)
#define CEXP 8.0f
#define KVB  (KVT * VSTK)              // halves per kv buffer
__global__ void __launch_bounds__(256) k_attn(float* __restrict__ out) {
    extern __shared__ char smc[];
    __half* k_s = (__half*)smc;                                // [3][64][136]
    __half* v_s = (__half*)(smc + 3 * KVB * 2);                // [3][64][136]
    __half* p_s = (__half*)(smc + 6 * KVB * 2);                // [2][128][72]
    int tid = threadIdx.x, w = tid >> 5, lane = tid & 31;
    int g = lane >> 2, q = lane & 3;
    int mi = lane >> 3, r = lane & 7;
    int mg = w >> 1, ng = w & 1;
    int b = blockIdx.z, h = blockIdx.y, qt = blockIdx.x;
    const __half* Q = g_q + ((size_t)(b * HH + h) * LL + (size_t)qt * 128) * DHD;
    const __half* K = g_k + (size_t)(b * HH + h) * MM * DHD;
    const __half* V = g_v + (size_t)(b * HH + h) * MM * DHD;
    // fragment lane offsets
    uint32_t aoffQ = ((mi & 1) * 8 + r) * VSTK + (mi >> 1) * 8;   // A-frag (Q / generic k-major)
    uint32_t boffK = ((mi >> 1) * 8 + r) * VSTK + (mi & 1) * 8;   // B-frag (K)
    uint32_t aoffP = ((mi & 1) * 8 + r) * PST + (mi >> 1) * 8;    // A-frag (P)
    int krow = ((lane >> 3) & 1) * 8 + (lane & 7);
    uint32_t voffb = krow * VSTK + (lane >> 4) * 8;               // B-frag (V, trans), col base added
    uint32_t loff  = (uint32_t)(lane & 15) * VSTK + 128;          // ones column
    int prow = ((lane >> 3) & 1) * 8 + (lane & 7);                // stmatrix row within 16
    int pcol = (lane >> 4) * 8;                                   // stmatrix col half

    // ---- ones into V pad cols (128..135) for all 3 buffers ----
    {
        __half2 one2 = __floats2half2_rn(1.f, 1.f);
        #pragma unroll
        for (int i = tid; i < 768; i += 256) {     // 3 buf * 64 rows * 4 half2
            int buf = i >> 8, rem = i & 255;
            int row = rem >> 2, p = rem & 3;
            *(__half2*)(v_s + buf * KVB + row * VSTK + 128 + p * 2) = one2;
        }
    }

    // ---- stage Q (128 rows x 128 halves = 2048 x 16B) across k_s buffers 0..1 ----
    #pragma unroll
    for (int i = 0; i < 8; i++) {
        int idx = tid + i * 256;                  // 0..2047
        int rr = idx >> 4, c = (idx & 15) * 8;    // rr 0..127, c halves 0..120
        cp16(k_s + rr * VSTK + c, Q + rr * DHD + c);
    }
    CPCOMMIT; CPWAIT(0);
    __syncthreads();
    unsigned qa[2][8][4];
    {
        uint32_t qu = smem_u32(k_s);
        #pragma unroll
        for (int i = 0; i < 2; i++)
            #pragma unroll
            for (int ks = 0; ks < 8; ks++)
                ldsm4(qa[i][ks], qu + 2 * ((mg * 32 + 16 * i) * VSTK + ks * 16 + aoffQ));
    }
    __syncthreads();

    auto loadkv = [&](int it) {
        int st = it % 3;
        __half* kd = k_s + st * KVB;
        __half* vd = v_s + st * KVB;
        const __half* ks = K + (size_t)it * KVT * DHD;
        const __half* vs = V + (size_t)it * KVT * DHD;
        #pragma unroll
        for (int i = 0; i < 4; i++) {
            int idx = tid + i * 256;                  // 0..1023
            int rr = idx >> 4, c = (idx & 15) * 8;    // rr 0..63
            cp16(kd + rr * VSTK + c, ks + rr * DHD + c);
            cp16(vd + rr * VSTK + c, vs + rr * DHD + c);
        }
        CPCOMMIT;
    };
    loadkv(0); loadkv(1);

    float o[2][8][4] = {};
    float ol[2][4] = {};

    #pragma unroll 1
    for (int it = 0; it < NIT; it++) {
        if (it < NIT - 1) CPWAIT(1); else CPWAIT(0);
        __syncthreads();                              // S1: tile it ready; P[it&1] free
        int st = it % 3;
        uint32_t ku = smem_u32(k_s + st * KVB);
        uint32_t vu = smem_u32(v_s + st * KVB);
        uint32_t pu = smem_u32(p_s + (it & 1) * 128 * PST);

        // ---- S = Q @ K^T : warp quadrant [32 rows][32 cols], init -CEXP ----
        float s[2][4][4];
        #pragma unroll
        for (int i = 0; i < 2; i++)
            #pragma unroll
            for (int j = 0; j < 4; j++) {
                s[i][j][0] = -CEXP; s[i][j][1] = -CEXP;
                s[i][j][2] = -CEXP; s[i][j][3] = -CEXP;
            }
        #pragma unroll
        for (int ks = 0; ks < 8; ks++) {
            #pragma unroll
            for (int j2 = 0; j2 < 2; j2++) {
                unsigned bf[4];
                ldsm4(bf, ku + 2 * ((ng * 32 + 16 * j2) * VSTK + ks * 16 + boffK));
                mma16f16(s[0][2 * j2],     qa[0][ks], bf[0], bf[1]);
                mma16f16(s[0][2 * j2 + 1], qa[0][ks], bf[2], bf[3]);
                mma16f16(s[1][2 * j2],     qa[1][ks], bf[0], bf[1]);
                mma16f16(s[1][2 * j2 + 1], qa[1][ks], bf[2], bf[3]);
            }
        }

        // ---- P = 2^s (fp32 ex2), store via stmatrix ----
        #pragma unroll
        for (int i = 0; i < 2; i++)
            #pragma unroll
            for (int jj = 0; jj < 2; jj++) {
                __half2 a0 = __floats2half2_rn(ex2f(s[i][2*jj][0]),   ex2f(s[i][2*jj][1]));
                __half2 a1 = __floats2half2_rn(ex2f(s[i][2*jj][2]),   ex2f(s[i][2*jj][3]));
                __half2 a2 = __floats2half2_rn(ex2f(s[i][2*jj+1][0]), ex2f(s[i][2*jj+1][1]));
                __half2 a3 = __floats2half2_rn(ex2f(s[i][2*jj+1][2]), ex2f(s[i][2*jj+1][3]));
                uint32_t pa = pu + 2 * ((mg * 32 + 16 * i + prow) * PST
                                        + ng * 32 + 16 * jj + pcol);
                stsm4(pa, *(unsigned*)&a0, *(unsigned*)&a1, *(unsigned*)&a2, *(unsigned*)&a3);
            }
        __syncthreads();                              // S2: P ready

        // ---- read P A-frags, O += P @ V, l via ones column ----
        unsigned pf[2][4][4];
        #pragma unroll
        for (int i = 0; i < 2; i++)
            #pragma unroll
            for (int kk = 0; kk < 4; kk++)
                ldsm4(pf[i][kk], pu + 2 * ((mg * 32 + 16 * i) * PST + kk * 16 + aoffP));
        #pragma unroll
        for (int kk = 0; kk < 4; kk++) {
            unsigned lb[2];
            ldsm2t(lb, vu + 2 * (16 * kk * VSTK + loff));
            mma16f16(ol[0], pf[0][kk], lb[0], lb[1]);
            mma16f16(ol[1], pf[1][kk], lb[0], lb[1]);
            #pragma unroll
            for (int nt = 0; nt < 4; nt++) {
                unsigned bf[4];
                ldsm4t(bf, vu + 2 * (16 * kk * VSTK + ng * 64 + 16 * nt + voffb));
                mma16f16(o[0][2 * nt],     pf[0][kk], bf[0], bf[1]);
                mma16f16(o[0][2 * nt + 1], pf[0][kk], bf[2], bf[3]);
                mma16f16(o[1][2 * nt],     pf[1][kk], bf[0], bf[1]);
                mma16f16(o[1][2 * nt + 1], pf[1][kk], bf[2], bf[3]);
            }
        }
        if (it + 2 < NIT) loadkv(it + 2);             // writes (it+2)%3, safe: readers done before S1(it)
    }

    // ---- epilogue: l exact from mma; direct float2 stores ----
    #pragma unroll
    for (int i = 0; i < 2; i++) {
        float inv0 = 1.f / ol[i][0];
        float inv1 = 1.f / ol[i][2];
        int r0 = qt * 128 + mg * 32 + 16 * i + g;
        #pragma unroll
        for (int j = 0; j < 8; j++) {
            int cc = h * DHD + ng * 64 + 8 * j + 2 * q;
            *(float2*)(out + (size_t)(b * LL + r0) * DD + cc) =
                make_float2(o[i][j][0] * inv0, o[i][j][1] * inv0);
            *(float2*)(out + (size_t)(b * LL + r0 + 8) * DD + cc) =
                make_float2(o[i][j][2] * inv1, o[i][j][3] * inv1);
        }
    }
}

// ------------------------- launch -------------------------
extern "C" void kernel_launch(void* const* d_in, const int* in_sizes, int n_in,
                              void* d_out, int out_size) {
    const float* ip   = (const float*)d_in[0];
    const float* q    = (const float*)d_in[1];
    const float* k    = (const float*)d_in[2];
    const float* v    = (const float*)d_in[3];
    const float* temb = (const float*)d_in[4];
    const float* Wada = (const float*)d_in[5];
    const float* bada = (const float*)d_in[6];
    const float* Wk   = (const float*)d_in[7];
    const float* Wv   = (const float*)d_in[8];
    const float* wq   = (const float*)d_in[9];
    const float* wk   = (const float*)d_in[10];
    const float* wipk = (const float*)d_in[11];
    float* out = (float*)d_out;

    k_round<<<DD * DD / 8 / 256, 256>>>(Wk, Wv);
    k_emb<<<(BB * TWOD) / 8, 256>>>(temb, Wada, bada);
    k_ipnorm<<<BB * LIP, 256>>>(ip);

    int gemm_smem = 2 * GNST * 128 * GST * sizeof(__half);   // 61440
    cudaFuncSetAttribute(k_gemm, cudaFuncAttributeMaxDynamicSharedMemorySize, gemm_smem);
    dim3 gg(DD / 128, (BB * LIP) / 128, 2);
    k_gemm<<<gg, 256, gemm_smem>>>();

    int totw = BB * HH * (LL * 3 + LIP * 2);
    k_scatter<<<totw / 8, 256>>>(q, k, v, wq, wk, wipk);

    int attn_smem = 6 * KVB * 2 + 2 * 128 * PST * 2;          // 104448 + 36864 = 141312
    cudaFuncSetAttribute(k_attn, cudaFuncAttributeMaxDynamicSharedMemorySize, attn_smem);
    dim3 ga(LL / 128, HH, BB);
    k_attn<<<ga, 256, attn_smem>>>(out);
}

// round 15
// speedup vs baseline: 1.0925x; 1.0925x over previous
#include <cuda_runtime.h>
#include <cuda_fp16.h>
#include <math.h>
#include <stdint.h>

#define BB   2
#define DD   2048
#define HH   16
#define DHD  128
#define TT   1280
#define LL   2048
#define LIP  512
#define MM   2560      // LL + LIP
#define TWOD 4096

// ------------------------- device scratch -------------------------
__device__ float  g_emb[BB * TWOD];
__device__ __half g_ipn[BB * LIP * DD];
__device__ float  g_ipk[BB * LIP * DD];
__device__ float  g_ipv[BB * LIP * DD];
__device__ __half g_wk[DD * DD];
__device__ __half g_wv[DD * DD];
__device__ __half g_q[(size_t)BB * HH * LL * DHD];        // fp16 q (rms * log2e/sqrt(d))
__device__ __half g_k[(size_t)BB * HH * MM * DHD];
__device__ __half g_v[(size_t)BB * HH * MM * DHD];

// ------------------------- helpers -------------------------
__device__ __forceinline__ void mma16f16(float* d, const unsigned* a, unsigned b0, unsigned b1) {
    asm volatile(
        "mma.sync.aligned.m16n8k16.row.col.f32.f16.f16.f32 "
        "{%0,%1,%2,%3},{%4,%5,%6,%7},{%8,%9},{%0,%1,%2,%3};"
        : "+f"(d[0]), "+f"(d[1]), "+f"(d[2]), "+f"(d[3])
        : "r"(a[0]), "r"(a[1]), "r"(a[2]), "r"(a[3]), "r"(b0), "r"(b1));
}
__device__ __forceinline__ void ldsm4(unsigned* r, uint32_t saddr) {
    asm volatile("ldmatrix.sync.aligned.m8n8.x4.shared.b16 {%0,%1,%2,%3}, [%4];"
        : "=r"(r[0]), "=r"(r[1]), "=r"(r[2]), "=r"(r[3]) : "r"(saddr));
}
__device__ __forceinline__ void ldsm4t(unsigned* r, uint32_t saddr) {
    asm volatile("ldmatrix.sync.aligned.m8n8.x4.trans.shared.b16 {%0,%1,%2,%3}, [%4];"
        : "=r"(r[0]), "=r"(r[1]), "=r"(r[2]), "=r"(r[3]) : "r"(saddr));
}
__device__ __forceinline__ float ex2f(float x) {
    float y; asm("ex2.approx.f32 %0, %1;" : "=f"(y) : "f"(x));
    return y;
}
__device__ __forceinline__ uint32_t smem_u32(const void* p) {
    return (uint32_t)__cvta_generic_to_shared(p);
}
__device__ __forceinline__ void cp16(void* s, const void* g) {
    unsigned a = (unsigned)__cvta_generic_to_shared(s);
    asm volatile("cp.async.cg.shared.global [%0], [%1], 16;" :: "r"(a), "l"(g));
}
#define CPCOMMIT asm volatile("cp.async.commit_group;")
#define CPWAIT(N) asm volatile("cp.async.wait_group %0;" :: "n"(N))

// ------------------------- kernel 0: weights -> fp16 -------------------------
__global__ void k_round(const float* __restrict__ Wk, const float* __restrict__ Wv) {
    int i = blockIdx.x * blockDim.x + threadIdx.x;
    float4 a0 = *(const float4*)(Wk + (size_t)i * 8);
    float4 a1 = *(const float4*)(Wk + (size_t)i * 8 + 4);
    float4 b0 = *(const float4*)(Wv + (size_t)i * 8);
    float4 b1 = *(const float4*)(Wv + (size_t)i * 8 + 4);
    __half2 ha[4] = { __floats2half2_rn(a0.x, a0.y), __floats2half2_rn(a0.z, a0.w),
                      __floats2half2_rn(a1.x, a1.y), __floats2half2_rn(a1.z, a1.w) };
    __half2 hb[4] = { __floats2half2_rn(b0.x, b0.y), __floats2half2_rn(b0.z, b0.w),
                      __floats2half2_rn(b1.x, b1.y), __floats2half2_rn(b1.z, b1.w) };
    *(uint4*)(g_wk + (size_t)i * 8) = *(uint4*)ha;
    *(uint4*)(g_wv + (size_t)i * 8) = *(uint4*)hb;
}

// ------------------------- kernel 1: emb -------------------------
__global__ void k_emb(const float* __restrict__ t_emb, const float* __restrict__ W,
                      const float* __restrict__ bias) {
    int gw   = (blockIdx.x * blockDim.x + threadIdx.x) >> 5;
    int lane = threadIdx.x & 31;
    int b = gw >> 12;
    int j = gw & 4095;
    const float* t = t_emb + b * TT;
    const float* w = W + (size_t)j * TT;
    float acc = 0.f;
    #pragma unroll
    for (int i = lane * 4; i < TT; i += 128) {
        float4 tv = *(const float4*)(t + i);
        float4 wv = *(const float4*)(w + i);
        acc += tv.x / (1.f + __expf(-tv.x)) * wv.x;
        acc += tv.y / (1.f + __expf(-tv.y)) * wv.y;
        acc += tv.z / (1.f + __expf(-tv.z)) * wv.z;
        acc += tv.w / (1.f + __expf(-tv.w)) * wv.w;
    }
    #pragma unroll
    for (int o = 16; o; o >>= 1) acc += __shfl_xor_sync(0xffffffffu, acc, o);
    if (lane == 0) g_emb[gw] = acc + bias[j];
}

// ------------------------- kernel 2: adaLN -> fp16 -------------------------
__global__ void k_ipnorm(const float* __restrict__ ip) {
    __shared__ float red[64];
    int row = blockIdx.x;
    int b = row / LIP;
    const float* x = ip + (size_t)row * DD;
    int i0 = threadIdx.x * 8;
    float4 v0 = *(const float4*)(x + i0);
    float4 v1 = *(const float4*)(x + i0 + 4);
    float s  = v0.x + v0.y + v0.z + v0.w + v1.x + v1.y + v1.z + v1.w;
    float ss = v0.x*v0.x + v0.y*v0.y + v0.z*v0.z + v0.w*v0.w
             + v1.x*v1.x + v1.y*v1.y + v1.z*v1.z + v1.w*v1.w;
    #pragma unroll
    for (int o = 16; o; o >>= 1) {
        s  += __shfl_xor_sync(0xffffffffu, s,  o);
        ss += __shfl_xor_sync(0xffffffffu, ss, o);
    }
    int w = threadIdx.x >> 5, lane = threadIdx.x & 31;
    if (lane == 0) { red[w] = s; red[32 + w] = ss; }
    __syncthreads();
    float fs = 0.f, fss = 0.f;
    #pragma unroll
    for (int k = 0; k < 8; k++) { fs += red[k]; fss += red[32 + k]; }
    float mu   = fs * (1.f / DD);
    float var  = fss * (1.f / DD) - mu * mu;
    float rstd = rsqrtf(var + 1e-6f);
    const float* shp = g_emb + b * TWOD;
    const float* scp = shp + DD;
    __half* y = g_ipn + (size_t)row * DD;
    float4 sh0 = *(const float4*)(shp + i0), sh1 = *(const float4*)(shp + i0 + 4);
    float4 sc0 = *(const float4*)(scp + i0), sc1 = *(const float4*)(scp + i0 + 4);
    __half2 h[4];
    h[0] = __floats2half2_rn((v0.x - mu) * rstd * (1.f + sc0.x) + sh0.x,
                             (v0.y - mu) * rstd * (1.f + sc0.y) + sh0.y);
    h[1] = __floats2half2_rn((v0.z - mu) * rstd * (1.f + sc0.z) + sh0.z,
                             (v0.w - mu) * rstd * (1.f + sc0.w) + sh0.w);
    h[2] = __floats2half2_rn((v1.x - mu) * rstd * (1.f + sc1.x) + sh1.x,
                             (v1.y - mu) * rstd * (1.f + sc1.y) + sh1.y);
    h[3] = __floats2half2_rn((v1.z - mu) * rstd * (1.f + sc1.z) + sh1.z,
                             (v1.w - mu) * rstd * (1.f + sc1.w) + sh1.w);
    *(uint4*)(y + i0) = *(uint4*)h;
}

// ------------------------- kernel 3: fp16 GEMM, fp32 accum (R9 structure) -------------------------
#define GST 40
#define GNST 3
__global__ void __launch_bounds__(256, 2) k_gemm() {
    extern __shared__ __half hsm[];
    __half* a_s = hsm;
    __half* b_s = hsm + GNST * 128 * GST;
    const __half* A  = g_ipn;
    const __half* Bw = blockIdx.z ? g_wv : g_wk;
    float*        C  = blockIdx.z ? g_ipv : g_ipk;
    int m0 = blockIdx.y * 128, n0 = blockIdx.x * 128;
    int tid = threadIdx.x, w = tid >> 5, lane = tid & 31;
    int g = lane >> 2, q = lane & 3;
    int mi = lane >> 3, r = lane & 7;
    int wm = (w & 3) * 32, wn = (w >> 2) * 64;
    uint32_t aoff = ((mi & 1) * 8 + r) * GST + (mi >> 1) * 8;
    uint32_t boff = ((mi >> 1) * 8 + r) * GST + (mi & 1) * 8;
    float c[2][8][4] = {};

    auto issue = [&](int ch) {
        int st = ch % GNST;
        __half* ad = a_s + st * 128 * GST;
        __half* bd = b_s + st * 128 * GST;
        #pragma unroll
        for (int i = 0; i < 2; i++) {
            int idx = tid + i * 256;
            int rr = idx >> 2, cc = (idx & 3) * 8;
            cp16(ad + rr * GST + cc, A  + (size_t)(m0 + rr) * DD + ch * 32 + cc);
            cp16(bd + rr * GST + cc, Bw + (size_t)(n0 + rr) * DD + ch * 32 + cc);
        }
        CPCOMMIT;
    };
    issue(0); issue(1);

    #pragma unroll 1
    for (int ch = 0; ch < 64; ch++) {
        if (ch < 63) CPWAIT(1); else CPWAIT(0);
        __syncthreads();
        int st = ch % GNST;
        uint32_t au = smem_u32(a_s + st * 128 * GST);
        uint32_t bu = smem_u32(b_s + st * 128 * GST);
        #pragma unroll
        for (int ks = 0; ks < 2; ks++) {
            unsigned af[2][4];
            #pragma unroll
            for (int i = 0; i < 2; i++)
                ldsm4(af[i], au + 2 * ((wm + 16 * i) * GST + ks * 16 + aoff));
            #pragma unroll
            for (int j2 = 0; j2 < 4; j2++) {
                unsigned bf[4];
                ldsm4(bf, bu + 2 * ((wn + 16 * j2) * GST + ks * 16 + boff));
                mma16f16(c[0][2 * j2],     af[0], bf[0], bf[1]);
                mma16f16(c[0][2 * j2 + 1], af[0], bf[2], bf[3]);
                mma16f16(c[1][2 * j2],     af[1], bf[0], bf[1]);
                mma16f16(c[1][2 * j2 + 1], af[1], bf[2], bf[3]);
            }
        }
        __syncthreads();
        if (ch + 2 < 64) issue(ch + 2);
    }
    #pragma unroll
    for (int i = 0; i < 2; i++)
        #pragma unroll
        for (int j = 0; j < 8; j++) {
            int r0 = m0 + wm + 16 * i + g, cc = n0 + wn + 8 * j + 2 * q;
            *(float2*)(C + (size_t)r0 * DD + cc)       = make_float2(c[i][j][0], c[i][j][1]);
            *(float2*)(C + (size_t)(r0 + 8) * DD + cc) = make_float2(c[i][j][2], c[i][j][3]);
        }
}

// ------------------------- kernel 4: RMS-norm + head split/scatter -> fp16 -------------------------
__global__ void k_scatter(const float* __restrict__ q, const float* __restrict__ k,
                          const float* __restrict__ v,
                          const float* __restrict__ wq, const float* __restrict__ wk,
                          const float* __restrict__ wipk) {
    int gw   = (blockIdx.x * blockDim.x + threadIdx.x) >> 5;
    int lane = threadIdx.x & 31;
    const int NQ  = BB * HH * LL;
    const int NIP = BB * HH * LIP;
    const float* src; __half* dst; const float* wptr = nullptr;
    float scale = 1.f; bool do_rms = false;

    int idx = gw;
    if (idx < NQ) {
        int b = idx / (HH * LL), r = idx % (HH * LL), h = r / LL, l = r % LL;
        src = q + (size_t)(b * LL + l) * DD + h * DHD;
        dst = g_q + (size_t)idx * DHD;
        wptr = wq; do_rms = true;
        scale = 1.4426950408889634f * 0.08838834764831845f;   // log2e / sqrt(128)
    } else if ((idx -= NQ) < NQ) {
        int b = idx / (HH * LL), r = idx % (HH * LL), h = r / LL, l = r % LL;
        src = k + (size_t)(b * LL + l) * DD + h * DHD;
        dst = g_k + ((size_t)(b * HH + h) * MM + l) * DHD;
        wptr = wk; do_rms = true;
    } else if ((idx -= NQ) < NIP) {
        int b = idx / (HH * LIP), r = idx % (HH * LIP), h = r / LIP, l = r % LIP;
        src = g_ipk + (size_t)(b * LIP + l) * DD + h * DHD;
        dst = g_k + ((size_t)(b * HH + h) * MM + LL + l) * DHD;
        wptr = wipk; do_rms = true;
    } else if ((idx -= NIP) < NQ) {
        int b = idx / (HH * LL), r = idx % (HH * LL), h = r / LL, l = r % LL;
        src = v + (size_t)(b * LL + l) * DD + h * DHD;
        dst = g_v + ((size_t)(b * HH + h) * MM + l) * DHD;
    } else {
        idx -= NQ;
        int b = idx / (HH * LIP), r = idx % (HH * LIP), h = r / LIP, l = r % LIP;
        src = g_ipv + (size_t)(b * LIP + l) * DD + h * DHD;
        dst = g_v + ((size_t)(b * HH + h) * MM + LL + l) * DHD;
    }

    float4 val = *(const float4*)(src + lane * 4);
    if (do_rms) {
        float ss = val.x*val.x + val.y*val.y + val.z*val.z + val.w*val.w;
        #pragma unroll
        for (int o = 16; o; o >>= 1) ss += __shfl_xor_sync(0xffffffffu, ss, o);
        float r = rsqrtf(ss * (1.f / DHD) + 1e-6f) * scale;
        float4 w4 = *(const float4*)(wptr + lane * 4);
        val.x *= r * w4.x; val.y *= r * w4.y; val.z *= r * w4.z; val.w *= r * w4.w;
    }
    __half2 h0 = __floats2half2_rn(val.x, val.y);
    __half2 h1 = __floats2half2_rn(val.z, val.w);
    *(__half2*)(dst + lane * 4)     = h0;
    *(__half2*)(dst + lane * 4 + 2) = h1;
}

// ------------------------- kernel 5: persistent flash attention (champion loop) -------------------------
// 304 persistent CTAs (2/SM), 128 threads (4 warps). Each CTA loops over (b,h,qt) tiles.
// Per tile: Q 64 rows, KV tile 64, double-buffered; fixed-max softmax P = 2^(s-8).
#define VSTK 136
#define KVT 64
#define NIT (MM / KVT)    // 40
#define KB16 (2 * KVT * VSTK * 2)   // 34816 B
#define CEXP 8.0f
#define NTILES (BB * HH * (LL / 64))  // 1024
__global__ void __launch_bounds__(128) k_attn(float* __restrict__ out) {
    extern __shared__ char smc[];
    __half* k_s = (__half*)smc;
    __half* v_s = (__half*)(smc + KB16);
    int tid = threadIdx.x, w = tid >> 5, lane = tid & 31;
    int g = lane >> 2, q = lane & 3;
    int mi = lane >> 3, r = lane & 7;
    uint32_t aoff = ((mi & 1) * 8 + r) * VSTK + (mi >> 1) * 8;    // A-frag (Q)
    uint32_t boff = ((mi >> 1) * 8 + r) * VSTK + (mi & 1) * 8;    // B-frag (K, k-major)
    int krow = ((lane >> 3) & 1) * 8 + (lane & 7);                // B-frag (V, trans)
    int ncol = (lane >> 4) * 8;
    uint32_t voff = krow * VSTK + ncol;

    #pragma unroll 1
    for (int tile = blockIdx.x; tile < NTILES; tile += gridDim.x) {
        int qt = tile & 31;            // 32 q-tiles per (b,h)
        int bh = tile >> 5;            // 0..31
        int h = bh & (HH - 1);
        int b = bh >> 4;
        const __half* Q = g_q + ((size_t)(b * HH + h) * LL + (size_t)qt * 64) * DHD;
        const __half* K = g_k + (size_t)(b * HH + h) * MM * DHD;
        const __half* V = g_v + (size_t)(b * HH + h) * MM * DHD;

        // ---- stage Q through k_s (64 rows x 128 halves = 1024 x 16B), read A-frags ----
        #pragma unroll
        for (int i = 0; i < 8; i++) {
            int idx = tid + i * 128;
            int rr = idx >> 4, c = (idx & 15) * 8;
            cp16(k_s + rr * VSTK + c, Q + rr * DHD + c);
        }
        CPCOMMIT; CPWAIT(0);
        __syncthreads();
        unsigned qa[8][4];
        {
            uint32_t qu = smem_u32(k_s);
            #pragma unroll
            for (int ks = 0; ks < 8; ks++)
                ldsm4(qa[ks], qu + 2 * (16 * w * VSTK + ks * 16 + aoff));
        }
        __syncthreads();

        auto loadkv = [&](int it) {
            int buf = it & 1;
            __half* kd = k_s + buf * KVT * VSTK;
            __half* vd = v_s + buf * KVT * VSTK;
            const __half* ks = K + (size_t)it * KVT * DHD;
            const __half* vs = V + (size_t)it * KVT * DHD;
            #pragma unroll
            for (int i = 0; i < 8; i++) {
                int idx = tid + i * 128;
                int rr = idx >> 4, c = (idx & 15) * 8;
                cp16(kd + rr * VSTK + c, ks + rr * DHD + c);
                cp16(vd + rr * VSTK + c, vs + rr * DHD + c);
            }
            CPCOMMIT;
        };
        loadkv(0); loadkv(1);

        float o[16][4] = {};
        float l0 = 0.f, l1 = 0.f;

        #pragma unroll 1
        for (int it = 0; it < NIT; it++) {
            if (it < NIT - 1) CPWAIT(1); else CPWAIT(0);
            __syncthreads();
            uint32_t ku = smem_u32(k_s + (it & 1) * KVT * VSTK);
            uint32_t vu = smem_u32(v_s + (it & 1) * KVT * VSTK);

            // ---- S = Q @ K^T (fp16, fp32 accum); ks outer for accumulator ILP ----
            float s[8][4] = {};
            #pragma unroll
            for (int ks = 0; ks < 8; ks++) {
                #pragma unroll
                for (int j2 = 0; j2 < 4; j2++) {
                    unsigned bf[4];
                    ldsm4(bf, ku + 2 * (16 * j2 * VSTK + ks * 16 + boff));
                    mma16f16(s[2 * j2],     qa[ks], bf[0], bf[1]);
                    mma16f16(s[2 * j2 + 1], qa[ks], bf[2], bf[3]);
                }
            }

            // ---- fixed-max softmax: P = 2^(s - C) ----
            #pragma unroll
            for (int j = 0; j < 8; j++) {
                s[j][0] = ex2f(s[j][0] - CEXP);
                s[j][1] = ex2f(s[j][1] - CEXP);
                s[j][2] = ex2f(s[j][2] - CEXP);
                s[j][3] = ex2f(s[j][3] - CEXP);
                l0 += s[j][0] + s[j][1];
                l1 += s[j][2] + s[j][3];
            }

            // ---- O += P @ V (fp16): S accumulator frag IS the fp16 A frag ----
            #pragma unroll
            for (int u = 0; u < 4; u++) {
                __half2 h0 = __floats2half2_rn(s[2*u][0],   s[2*u][1]);
                __half2 h1 = __floats2half2_rn(s[2*u][2],   s[2*u][3]);
                __half2 h2 = __floats2half2_rn(s[2*u+1][0], s[2*u+1][1]);
                __half2 h3 = __floats2half2_rn(s[2*u+1][2], s[2*u+1][3]);
                unsigned pa[4] = { *(unsigned*)&h0, *(unsigned*)&h1,
                                   *(unsigned*)&h2, *(unsigned*)&h3 };
                #pragma unroll
                for (int nt2 = 0; nt2 < 8; nt2++) {
                    unsigned bf[4];
                    ldsm4t(bf, vu + 2 * (16 * u * VSTK + 16 * nt2 + voff));
                    mma16f16(o[2 * nt2],     pa, bf[0], bf[1]);
                    mma16f16(o[2 * nt2 + 1], pa, bf[2], bf[3]);
                }
            }
            __syncthreads();
            if (it + 2 < NIT) loadkv(it + 2);
        }

        // ---- epilogue ----
        l0 += __shfl_xor_sync(0xffffffffu, l0, 1);
        l0 += __shfl_xor_sync(0xffffffffu, l0, 2);
        l1 += __shfl_xor_sync(0xffffffffu, l1, 1);
        l1 += __shfl_xor_sync(0xffffffffu, l1, 2);
        float inv0 = 1.f / l0, inv1 = 1.f / l1;
        __syncthreads();                          // all warps done reading KV buffers
        float* o_s = (float*)smc;                 // 64 rows x stride 132 floats
        int r0 = 16 * w + g;
        #pragma unroll
        for (int nt = 0; nt < 16; nt++) {
            int cc = 8 * nt + 2 * q;
            o_s[r0 * 132 + cc]           = o[nt][0] * inv0;
            o_s[r0 * 132 + cc + 1]       = o[nt][1] * inv0;
            o_s[(r0 + 8) * 132 + cc]     = o[nt][2] * inv1;
            o_s[(r0 + 8) * 132 + cc + 1] = o[nt][3] * inv1;
        }
        __syncthreads();
        #pragma unroll
        for (int i = 0; i < 16; i++) {
            int idx = tid + i * 128;
            int rr = idx >> 5, c = (idx & 31) * 4;
            *(float4*)(out + ((size_t)(b * LL + qt * 64 + rr)) * DD + h * DHD + c) =
                *(const float4*)(o_s + rr * 132 + c);
        }
        __syncthreads();                          // protect o_s before next tile's Q staging
    }
}

// ------------------------- launch -------------------------
extern "C" void kernel_launch(void* const* d_in, const int* in_sizes, int n_in,
                              void* d_out, int out_size) {
    const float* ip   = (const float*)d_in[0];
    const float* q    = (const float*)d_in[1];
    const float* k    = (const float*)d_in[2];
    const float* v    = (const float*)d_in[3];
    const float* temb = (const float*)d_in[4];
    const float* Wada = (const float*)d_in[5];
    const float* bada = (const float*)d_in[6];
    const float* Wk   = (const float*)d_in[7];
    const float* Wv   = (const float*)d_in[8];
    const float* wq   = (const float*)d_in[9];
    const float* wk   = (const float*)d_in[10];
    const float* wipk = (const float*)d_in[11];
    float* out = (float*)d_out;

    k_round<<<DD * DD / 8 / 256, 256>>>(Wk, Wv);
    k_emb<<<(BB * TWOD) / 8, 256>>>(temb, Wada, bada);
    k_ipnorm<<<BB * LIP, 256>>>(ip);

    int gemm_smem = 2 * GNST * 128 * GST * sizeof(__half);   // 61440
    cudaFuncSetAttribute(k_gemm, cudaFuncAttributeMaxDynamicSharedMemorySize, gemm_smem);
    dim3 gg(DD / 128, (BB * LIP) / 128, 2);
    k_gemm<<<gg, 256, gemm_smem>>>();

    int totw = BB * HH * (LL * 3 + LIP * 2);
    k_scatter<<<totw / 8, 256>>>(q, k, v, wq, wk, wipk);

    int attn_smem = 2 * KB16;                                 // 69632
    cudaFuncSetAttribute(k_attn, cudaFuncAttributeMaxDynamicSharedMemorySize, attn_smem);
    k_attn<<<304, 128, attn_smem>>>(out);                     // persistent: 2 CTAs x 152 SMs
}

// round 17
// speedup vs baseline: 1.1106x; 1.0166x over previous
#include <cuda_runtime.h>
#include <cuda_fp16.h>
#include <math.h>
#include <stdint.h>

#define BB   2
#define DD   2048
#define HH   16
#define DHD  128
#define TT   1280
#define LL   2048
#define LIP  512
#define MM   2560      // LL + LIP
#define TWOD 4096

// ------------------------- device scratch -------------------------
__device__ float  g_emb[BB * TWOD];
__device__ __half g_ipn[BB * LIP * DD];
__device__ float  g_ipk[BB * LIP * DD];
__device__ float  g_ipv[BB * LIP * DD];
__device__ __half g_wk[DD * DD];
__device__ __half g_wv[DD * DD];
__device__ __half g_q[(size_t)BB * HH * LL * DHD];        // fp16 q (rms * log2e/sqrt(d))
__device__ __half g_k[(size_t)BB * HH * MM * DHD];
__device__ __half g_v[(size_t)BB * HH * MM * DHD];

// ------------------------- helpers -------------------------
__device__ __forceinline__ void mma16f16(float* d, const unsigned* a, unsigned b0, unsigned b1) {
    asm volatile(
        "mma.sync.aligned.m16n8k16.row.col.f32.f16.f16.f32 "
        "{%0,%1,%2,%3},{%4,%5,%6,%7},{%8,%9},{%0,%1,%2,%3};"
        : "+f"(d[0]), "+f"(d[1]), "+f"(d[2]), "+f"(d[3])
        : "r"(a[0]), "r"(a[1]), "r"(a[2]), "r"(a[3]), "r"(b0), "r"(b1));
}
__device__ __forceinline__ void ldsm4(unsigned* r, uint32_t saddr) {
    asm volatile("ldmatrix.sync.aligned.m8n8.x4.shared.b16 {%0,%1,%2,%3}, [%4];"
        : "=r"(r[0]), "=r"(r[1]), "=r"(r[2]), "=r"(r[3]) : "r"(saddr));
}
__device__ __forceinline__ void ldsm4t(unsigned* r, uint32_t saddr) {
    asm volatile("ldmatrix.sync.aligned.m8n8.x4.trans.shared.b16 {%0,%1,%2,%3}, [%4];"
        : "=r"(r[0]), "=r"(r[1]), "=r"(r[2]), "=r"(r[3]) : "r"(saddr));
}
__device__ __forceinline__ float ex2f(float x) {
    float y; asm("ex2.approx.f32 %0, %1;" : "=f"(y) : "f"(x));
    return y;
}
__device__ __forceinline__ uint32_t smem_u32(const void* p) {
    return (uint32_t)__cvta_generic_to_shared(p);
}
__device__ __forceinline__ void cp16(void* s, const void* g) {
    unsigned a = (unsigned)__cvta_generic_to_shared(s);
    asm volatile("cp.async.cg.shared.global [%0], [%1], 16;" :: "r"(a), "l"(g));
}
#define CPCOMMIT asm volatile("cp.async.commit_group;")
#define CPWAIT(N) asm volatile("cp.async.wait_group %0;" :: "n"(N))

// ------------------------- kernel 0: weights -> fp16 -------------------------
__global__ void k_round(const float* __restrict__ Wk, const float* __restrict__ Wv) {
    int i = blockIdx.x * blockDim.x + threadIdx.x;
    float4 a0 = *(const float4*)(Wk + (size_t)i * 8);
    float4 a1 = *(const float4*)(Wk + (size_t)i * 8 + 4);
    float4 b0 = *(const float4*)(Wv + (size_t)i * 8);
    float4 b1 = *(const float4*)(Wv + (size_t)i * 8 + 4);
    __half2 ha[4] = { __floats2half2_rn(a0.x, a0.y), __floats2half2_rn(a0.z, a0.w),
                      __floats2half2_rn(a1.x, a1.y), __floats2half2_rn(a1.z, a1.w) };
    __half2 hb[4] = { __floats2half2_rn(b0.x, b0.y), __floats2half2_rn(b0.z, b0.w),
                      __floats2half2_rn(b1.x, b1.y), __floats2half2_rn(b1.z, b1.w) };
    *(uint4*)(g_wk + (size_t)i * 8) = *(uint4*)ha;
    *(uint4*)(g_wv + (size_t)i * 8) = *(uint4*)hb;
}

// ------------------------- kernel 1: emb -------------------------
__global__ void k_emb(const float* __restrict__ t_emb, const float* __restrict__ W,
                      const float* __restrict__ bias) {
    int gw   = (blockIdx.x * blockDim.x + threadIdx.x) >> 5;
    int lane = threadIdx.x & 31;
    int b = gw >> 12;
    int j = gw & 4095;
    const float* t = t_emb + b * TT;
    const float* w = W + (size_t)j * TT;
    float acc = 0.f;
    #pragma unroll
    for (int i = lane * 4; i < TT; i += 128) {
        float4 tv = *(const float4*)(t + i);
        float4 wv = *(const float4*)(w + i);
        acc += tv.x / (1.f + __expf(-tv.x)) * wv.x;
        acc += tv.y / (1.f + __expf(-tv.y)) * wv.y;
        acc += tv.z / (1.f + __expf(-tv.z)) * wv.z;
        acc += tv.w / (1.f + __expf(-tv.w)) * wv.w;
    }
    #pragma unroll
    for (int o = 16; o; o >>= 1) acc += __shfl_xor_sync(0xffffffffu, acc, o);
    if (lane == 0) g_emb[gw] = acc + bias[j];
}

// ------------------------- kernel 2: adaLN -> fp16 -------------------------
__global__ void k_ipnorm(const float* __restrict__ ip) {
    __shared__ float red[64];
    int row = blockIdx.x;
    int b = row / LIP;
    const float* x = ip + (size_t)row * DD;
    int i0 = threadIdx.x * 8;
    float4 v0 = *(const float4*)(x + i0);
    float4 v1 = *(const float4*)(x + i0 + 4);
    float s  = v0.x + v0.y + v0.z + v0.w + v1.x + v1.y + v1.z + v1.w;
    float ss = v0.x*v0.x + v0.y*v0.y + v0.z*v0.z + v0.w*v0.w
             + v1.x*v1.x + v1.y*v1.y + v1.z*v1.z + v1.w*v1.w;
    #pragma unroll
    for (int o = 16; o; o >>= 1) {
        s  += __shfl_xor_sync(0xffffffffu, s,  o);
        ss += __shfl_xor_sync(0xffffffffu, ss, o);
    }
    int w = threadIdx.x >> 5, lane = threadIdx.x & 31;
    if (lane == 0) { red[w] = s; red[32 + w] = ss; }
    __syncthreads();
    float fs = 0.f, fss = 0.f;
    #pragma unroll
    for (int k = 0; k < 8; k++) { fs += red[k]; fss += red[32 + k]; }
    float mu   = fs * (1.f / DD);
    float var  = fss * (1.f / DD) - mu * mu;
    float rstd = rsqrtf(var + 1e-6f);
    const float* shp = g_emb + b * TWOD;
    const float* scp = shp + DD;
    __half* y = g_ipn + (size_t)row * DD;
    float4 sh0 = *(const float4*)(shp + i0), sh1 = *(const float4*)(shp + i0 + 4);
    float4 sc0 = *(const float4*)(scp + i0), sc1 = *(const float4*)(scp + i0 + 4);
    __half2 h[4];
    h[0] = __floats2half2_rn((v0.x - mu) * rstd * (1.f + sc0.x) + sh0.x,
                             (v0.y - mu) * rstd * (1.f + sc0.y) + sh0.y);
    h[1] = __floats2half2_rn((v0.z - mu) * rstd * (1.f + sc0.z) + sh0.z,
                             (v0.w - mu) * rstd * (1.f + sc0.w) + sh0.w);
    h[2] = __floats2half2_rn((v1.x - mu) * rstd * (1.f + sc1.x) + sh1.x,
                             (v1.y - mu) * rstd * (1.f + sc1.y) + sh1.y);
    h[3] = __floats2half2_rn((v1.z - mu) * rstd * (1.f + sc1.z) + sh1.z,
                             (v1.w - mu) * rstd * (1.f + sc1.w) + sh1.w);
    *(uint4*)(y + i0) = *(uint4*)h;
}

// ------------------------- kernel 3: fp16 GEMM, 64-half k-chunks, 3-stage -------------------------
#define GST 72            // 64 halves + 8 pad
#define GNST 3
#define GCH  32           // 2048 / 64
__global__ void __launch_bounds__(256, 2) k_gemm() {
    extern __shared__ __half hsm[];
    __half* a_s = hsm;                        // [3][128][72]
    __half* b_s = hsm + GNST * 128 * GST;     // [3][128][72]
    const __half* A  = g_ipn;
    const __half* Bw = blockIdx.z ? g_wv : g_wk;
    float*        C  = blockIdx.z ? g_ipv : g_ipk;
    int m0 = blockIdx.y * 128, n0 = blockIdx.x * 128;
    int tid = threadIdx.x, w = tid >> 5, lane = tid & 31;
    int g = lane >> 2, q = lane & 3;
    int mi = lane >> 3, r = lane & 7;
    int wm = (w & 3) * 32, wn = (w >> 2) * 64;
    uint32_t aoff = ((mi & 1) * 8 + r) * GST + (mi >> 1) * 8;
    uint32_t boff = ((mi >> 1) * 8 + r) * GST + (mi & 1) * 8;
    float c[2][8][4] = {};

    auto issue = [&](int ch) {
        int st = ch % GNST;
        __half* ad = a_s + st * 128 * GST;
        __half* bd = b_s + st * 128 * GST;
        #pragma unroll
        for (int i = 0; i < 4; i++) {
            int idx = tid + i * 256;              // 0..1023 = 128 rows x 8 chunks
            int rr = idx >> 3, cc = (idx & 7) * 8;
            cp16(ad + rr * GST + cc, A  + (size_t)(m0 + rr) * DD + ch * 64 + cc);
            cp16(bd + rr * GST + cc, Bw + (size_t)(n0 + rr) * DD + ch * 64 + cc);
        }
        CPCOMMIT;
    };
    issue(0); issue(1);

    #pragma unroll 1
    for (int ch = 0; ch < GCH; ch++) {
        if (ch < GCH - 1) CPWAIT(1); else CPWAIT(0);
        __syncthreads();
        int st = ch % GNST;
        uint32_t au = smem_u32(a_s + st * 128 * GST);
        uint32_t bu = smem_u32(b_s + st * 128 * GST);
        #pragma unroll
        for (int ks = 0; ks < 4; ks++) {
            unsigned af[2][4];
            #pragma unroll
            for (int i = 0; i < 2; i++)
                ldsm4(af[i], au + 2 * ((wm + 16 * i) * GST + ks * 16 + aoff));
            #pragma unroll
            for (int j2 = 0; j2 < 4; j2++) {
                unsigned bf[4];
                ldsm4(bf, bu + 2 * ((wn + 16 * j2) * GST + ks * 16 + boff));
                mma16f16(c[0][2 * j2],     af[0], bf[0], bf[1]);
                mma16f16(c[0][2 * j2 + 1], af[0], bf[2], bf[3]);
                mma16f16(c[1][2 * j2],     af[1], bf[0], bf[1]);
                mma16f16(c[1][2 * j2 + 1], af[1], bf[2], bf[3]);
            }
        }
        __syncthreads();
        if (ch + 2 < GCH) issue(ch + 2);
    }
    #pragma unroll
    for (int i = 0; i < 2; i++)
        #pragma unroll
        for (int j = 0; j < 8; j++) {
            int r0 = m0 + wm + 16 * i + g, cc = n0 + wn + 8 * j + 2 * q;
            *(float2*)(C + (size_t)r0 * DD + cc)       = make_float2(c[i][j][0], c[i][j][1]);
            *(float2*)(C + (size_t)(r0 + 8) * DD + cc) = make_float2(c[i][j][2], c[i][j][3]);
        }
}

// ------------------------- kernel 4: RMS-norm + head split/scatter -> fp16 -------------------------
__global__ void k_scatter(const float* __restrict__ q, const float* __restrict__ k,
                          const float* __restrict__ v,
                          const float* __restrict__ wq, const float* __restrict__ wk,
                          const float* __restrict__ wipk) {
    int gw   = (blockIdx.x * blockDim.x + threadIdx.x) >> 5;
    int lane = threadIdx.x & 31;
    const int NQ  = BB * HH * LL;
    const int NIP = BB * HH * LIP;
    const float* src; __half* dst; const float* wptr = nullptr;
    float scale = 1.f; bool do_rms = false;

    int idx = gw;
    if (idx < NQ) {
        int b = idx / (HH * LL), r = idx % (HH * LL), h = r / LL, l = r % LL;
        src = q + (size_t)(b * LL + l) * DD + h * DHD;
        dst = g_q + (size_t)idx * DHD;
        wptr = wq; do_rms = true;
        scale = 1.4426950408889634f * 0.08838834764831845f;   // log2e / sqrt(128)
    } else if ((idx -= NQ) < NQ) {
        int b = idx / (HH * LL), r = idx % (HH * LL), h = r / LL, l = r % LL;
        src = k + (size_t)(b * LL + l) * DD + h * DHD;
        dst = g_k + ((size_t)(b * HH + h) * MM + l) * DHD;
        wptr = wk; do_rms = true;
    } else if ((idx -= NQ) < NIP) {
        int b = idx / (HH * LIP), r = idx % (HH * LIP), h = r / LIP, l = r % LIP;
        src = g_ipk + (size_t)(b * LIP + l) * DD + h * DHD;
        dst = g_k + ((size_t)(b * HH + h) * MM + LL + l) * DHD;
        wptr = wipk; do_rms = true;
    } else if ((idx -= NIP) < NQ) {
        int b = idx / (HH * LL), r = idx % (HH * LL), h = r / LL, l = r % LL;
        src = v + (size_t)(b * LL + l) * DD + h * DHD;
        dst = g_v + ((size_t)(b * HH + h) * MM + l) * DHD;
    } else {
        idx -= NQ;
        int b = idx / (HH * LIP), r = idx % (HH * LIP), h = r / LIP, l = r % LIP;
        src = g_ipv + (size_t)(b * LIP + l) * DD + h * DHD;
        dst = g_v + ((size_t)(b * HH + h) * MM + LL + l) * DHD;
    }

    float4 val = *(const float4*)(src + lane * 4);
    if (do_rms) {
        float ss = val.x*val.x + val.y*val.y + val.z*val.z + val.w*val.w;
        #pragma unroll
        for (int o = 16; o; o >>= 1) ss += __shfl_xor_sync(0xffffffffu, ss, o);
        float r = rsqrtf(ss * (1.f / DHD) + 1e-6f) * scale;
        float4 w4 = *(const float4*)(wptr + lane * 4);
        val.x *= r * w4.x; val.y *= r * w4.y; val.z *= r * w4.z; val.w *= r * w4.w;
    }
    __half2 h0 = __floats2half2_rn(val.x, val.y);
    __half2 h1 = __floats2half2_rn(val.z, val.w);
    *(__half2*)(dst + lane * 4)     = h0;
    *(__half2*)(dst + lane * 4 + 2) = h1;
}

// ------------------------- kernel 5: persistent flash attention, 3-stage single-sync -------------------------
// 304 persistent CTAs (2/SM), 128 threads (4 warps). Per tile: Q 64 rows, KV tile 64.
// 3-stage KV ring, ONE sync per iteration, loads issued at loop bottom (after compute).
#define VSTK 136
#define KVT 64
#define NIT (MM / KVT)    // 40
#define KVB (KVT * VSTK)                // halves per buffer (8704)
#define CEXP 8.0f
#define NTILES (BB * HH * (LL / 64))    // 1024
__global__ void __launch_bounds__(128) k_attn(float* __restrict__ out) {
    extern __shared__ char smc[];
    __half* k_s = (__half*)smc;                        // [3][64][136]
    __half* v_s = (__half*)(smc + 3 * KVB * 2);        // [3][64][136]
    int tid = threadIdx.x, w = tid >> 5, lane = tid & 31;
    int g = lane >> 2, q = lane & 3;
    int mi = lane >> 3, r = lane & 7;
    uint32_t aoff = ((mi & 1) * 8 + r) * VSTK + (mi >> 1) * 8;    // A-frag (Q)
    uint32_t boff = ((mi >> 1) * 8 + r) * VSTK + (mi & 1) * 8;    // B-frag (K, k-major)
    int krow = ((lane >> 3) & 1) * 8 + (lane & 7);                // B-frag (V, trans)
    int ncol = (lane >> 4) * 8;
    uint32_t voff = krow * VSTK + ncol;

    #pragma unroll 1
    for (int tile = blockIdx.x; tile < NTILES; tile += gridDim.x) {
        int qt = tile & 31;
        int bh = tile >> 5;
        int h = bh & (HH - 1);
        int b = bh >> 4;
        const __half* Q = g_q + ((size_t)(b * HH + h) * LL + (size_t)qt * 64) * DHD;
        const __half* K = g_k + (size_t)(b * HH + h) * MM * DHD;
        const __half* V = g_v + (size_t)(b * HH + h) * MM * DHD;

        // ---- stage Q through k_s (64 rows x 128 halves), read A-frags ----
        #pragma unroll
        for (int i = 0; i < 8; i++) {
            int idx = tid + i * 128;
            int rr = idx >> 4, c = (idx & 15) * 8;
            cp16(k_s + rr * VSTK + c, Q + rr * DHD + c);
        }
        CPCOMMIT; CPWAIT(0);
        __syncthreads();
        unsigned qa[8][4];
        {
            uint32_t qu = smem_u32(k_s);
            #pragma unroll
            for (int ks = 0; ks < 8; ks++)
                ldsm4(qa[ks], qu + 2 * (16 * w * VSTK + ks * 16 + aoff));
        }
        __syncthreads();

        auto loadkv = [&](int it) {
            int st = it % 3;
            __half* kd = k_s + st * KVB;
            __half* vd = v_s + st * KVB;
            const __half* ks = K + (size_t)it * KVT * DHD;
            const __half* vs = V + (size_t)it * KVT * DHD;
            #pragma unroll
            for (int i = 0; i < 8; i++) {
                int idx = tid + i * 128;
                int rr = idx >> 4, c = (idx & 15) * 8;
                cp16(kd + rr * VSTK + c, ks + rr * DHD + c);
                cp16(vd + rr * VSTK + c, vs + rr * DHD + c);
            }
            CPCOMMIT;
        };
        loadkv(0); loadkv(1);

        float o[16][4] = {};
        float l0 = 0.f, l1 = 0.f;

        #pragma unroll 1
        for (int it = 0; it < NIT; it++) {
            if (it < NIT - 1) CPWAIT(1); else CPWAIT(0);
            __syncthreads();                      // tile it ready; also fences it-1 reads CTA-wide
            int st = it % 3;
            uint32_t ku = smem_u32(k_s + st * KVB);
            uint32_t vu = smem_u32(v_s + st * KVB);

            // ---- S = Q @ K^T ----
            float s[8][4] = {};
            #pragma unroll
            for (int ks = 0; ks < 8; ks++) {
                #pragma unroll
                for (int j2 = 0; j2 < 4; j2++) {
                    unsigned bf[4];
                    ldsm4(bf, ku + 2 * (16 * j2 * VSTK + ks * 16 + boff));
                    mma16f16(s[2 * j2],     qa[ks], bf[0], bf[1]);
                    mma16f16(s[2 * j2 + 1], qa[ks], bf[2], bf[3]);
                }
            }

            // ---- fixed-max softmax: P = 2^(s - C) ----
            #pragma unroll
            for (int j = 0; j < 8; j++) {
                s[j][0] = ex2f(s[j][0] - CEXP);
                s[j][1] = ex2f(s[j][1] - CEXP);
                s[j][2] = ex2f(s[j][2] - CEXP);
                s[j][3] = ex2f(s[j][3] - CEXP);
                l0 += s[j][0] + s[j][1];
                l1 += s[j][2] + s[j][3];
            }

            // ---- O += P @ V ----
            #pragma unroll
            for (int u = 0; u < 4; u++) {
                __half2 h0 = __floats2half2_rn(s[2*u][0],   s[2*u][1]);
                __half2 h1 = __floats2half2_rn(s[2*u][2],   s[2*u][3]);
                __half2 h2 = __floats2half2_rn(s[2*u+1][0], s[2*u+1][1]);
                __half2 h3 = __floats2half2_rn(s[2*u+1][2], s[2*u+1][3]);
                unsigned pa[4] = { *(unsigned*)&h0, *(unsigned*)&h1,
                                   *(unsigned*)&h2, *(unsigned*)&h3 };
                #pragma unroll
                for (int nt2 = 0; nt2 < 8; nt2++) {
                    unsigned bf[4];
                    ldsm4t(bf, vu + 2 * (16 * u * VSTK + 16 * nt2 + voff));
                    mma16f16(o[2 * nt2],     pa, bf[0], bf[1]);
                    mma16f16(o[2 * nt2 + 1], pa, bf[2], bf[3]);
                }
            }
            // bottom: prefetch into (it+2)%3 == (it-1)%3 — freed by this iteration's top sync
            if (it + 2 < NIT) loadkv(it + 2);
        }

        // ---- epilogue ----
        l0 += __shfl_xor_sync(0xffffffffu, l0, 1);
        l0 += __shfl_xor_sync(0xffffffffu, l0, 2);
        l1 += __shfl_xor_sync(0xffffffffu, l1, 1);
        l1 += __shfl_xor_sync(0xffffffffu, l1, 2);
        float inv0 = 1.f / l0, inv1 = 1.f / l1;
        __syncthreads();                          // all warps done reading KV smem
        float* o_s = (float*)smc;                 // 64 rows x stride 132 floats
        int r0 = 16 * w + g;
        #pragma unroll
        for (int nt = 0; nt < 16; nt++) {
            int cc = 8 * nt + 2 * q;
            o_s[r0 * 132 + cc]           = o[nt][0] * inv0;
            o_s[r0 * 132 + cc + 1]       = o[nt][1] * inv0;
            o_s[(r0 + 8) * 132 + cc]     = o[nt][2] * inv1;
            o_s[(r0 + 8) * 132 + cc + 1] = o[nt][3] * inv1;
        }
        __syncthreads();
        #pragma unroll
        for (int i = 0; i < 16; i++) {
            int idx = tid + i * 128;
            int rr = idx >> 5, c = (idx & 31) * 4;
            *(float4*)(out + ((size_t)(b * LL + qt * 64 + rr)) * DD + h * DHD + c) =
                *(const float4*)(o_s + rr * 132 + c);
        }
        __syncthreads();                          // protect o_s before next tile's Q staging
    }
}

// ------------------------- launch -------------------------
extern "C" void kernel_launch(void* const* d_in, const int* in_sizes, int n_in,
                              void* d_out, int out_size) {
    const float* ip   = (const float*)d_in[0];
    const float* q    = (const float*)d_in[1];
    const float* k    = (const float*)d_in[2];
    const float* v    = (const float*)d_in[3];
    const float* temb = (const float*)d_in[4];
    const float* Wada = (const float*)d_in[5];
    const float* bada = (const float*)d_in[6];
    const float* Wk   = (const float*)d_in[7];
    const float* Wv   = (const float*)d_in[8];
    const float* wq   = (const float*)d_in[9];
    const float* wk   = (const float*)d_in[10];
    const float* wipk = (const float*)d_in[11];
    float* out = (float*)d_out;

    k_round<<<DD * DD / 8 / 256, 256>>>(Wk, Wv);
    k_emb<<<(BB * TWOD) / 8, 256>>>(temb, Wada, bada);
    k_ipnorm<<<BB * LIP, 256>>>(ip);

    int gemm_smem = 2 * GNST * 128 * GST * sizeof(__half);   // 110592
    cudaFuncSetAttribute(k_gemm, cudaFuncAttributeMaxDynamicSharedMemorySize, gemm_smem);
    dim3 gg(DD / 128, (BB * LIP) / 128, 2);
    k_gemm<<<gg, 256, gemm_smem>>>();

    int totw = BB * HH * (LL * 3 + LIP * 2);
    k_scatter<<<totw / 8, 256>>>(q, k, v, wq, wk, wipk);

    int attn_smem = 2 * 3 * KVB * (int)sizeof(__half);        // k_s + v_s: 104448 bytes
    cudaFuncSetAttribute(k_attn, cudaFuncAttributeMaxDynamicSharedMemorySize, attn_smem);
    k_attn<<<304, 128, attn_smem>>>(out);                     // persistent: 2 CTAs x 152 SMs
}